// round 15
// baseline (speedup 1.0000x reference)
#include <cuda_runtime.h>
#include <cuda_fp16.h>
#include <cstdint>

// Problem constants: B=2, S=2048, DM=1024, H=16, DH=64
#define BATCH 2
#define SEQ 2048
#define DMODEL 1024
#define HEADS 16
#define HDIM 64
#define MROWS (BATCH*SEQ)                 // 4096
#define QKV_ELEMS (BATCH*HEADS*SEQ*HDIM)  // 4,194,304

// Q prescale: 0.125 * log2(e)  (scores arrive in exp2 domain)
#define QSCALE 0.18033688011112042f
#define RAWSCALE 5.5451774444795623f

// ---------------- device scratch (fp16) ----------------
__device__ __half g_x16[MROWS * DMODEL];
__device__ __half g_w16[3 * DMODEL * DMODEL];
__device__ __half g_q16[QKV_ELEMS];
__device__ __half g_k16[QKV_ELEMS];
__device__ __half g_v16[QKV_ELEMS];
// absmax slots: 0=q 1=k 2=qk_raw 3=aw 4=v
__device__ unsigned g_mx[5];

// ---------------- helpers ----------------
__device__ __forceinline__ void mma_f16(float (&c)[4], const uint32_t (&a)[4],
                                        uint32_t b0, uint32_t b1) {
    asm volatile(
        "mma.sync.aligned.m16n8k16.row.col.f32.f16.f16.f32 "
        "{%0,%1,%2,%3}, {%4,%5,%6,%7}, {%8,%9}, {%0,%1,%2,%3};"
        : "+f"(c[0]), "+f"(c[1]), "+f"(c[2]), "+f"(c[3])
        : "r"(a[0]), "r"(a[1]), "r"(a[2]), "r"(a[3]), "r"(b0), "r"(b1));
}
__device__ __forceinline__ uint32_t packh(float lo, float hi) {
    uint32_t r;
    asm("cvt.rn.f16x2.f32 %0, %1, %2;" : "=r"(r) : "f"(hi), "f"(lo));
    return r;
}
__device__ __forceinline__ uint32_t ex2_h2(uint32_t a) {
    uint32_t r;
    asm("ex2.approx.f16x2 %0, %1;" : "=r"(r) : "r"(a));
    return r;
}
__device__ __forceinline__ uint32_t smem_u32(const void* p) {
    uint32_t a;
    asm("{ .reg .u64 t; cvta.to.shared.u64 t, %1; cvt.u32.u64 %0, t; }"
        : "=r"(a) : "l"(p));
    return a;
}
#define LDSM_X4(r0, r1, r2, r3, addr) \
    asm volatile("ldmatrix.sync.aligned.m8n8.x4.shared.b16 {%0,%1,%2,%3}, [%4];" \
                 : "=r"(r0), "=r"(r1), "=r"(r2), "=r"(r3) : "r"(addr))
#define LDSM_X4_T(r0, r1, r2, r3, addr) \
    asm volatile("ldmatrix.sync.aligned.m8n8.x4.trans.shared.b16 {%0,%1,%2,%3}, [%4];" \
                 : "=r"(r0), "=r"(r1), "=r"(r2), "=r"(r3) : "r"(addr))
#define CP_ASYNC16(dst, src) \
    asm volatile("cp.async.cg.shared.global [%0], [%1], 16;" \
                 :: "r"(dst), "l"(src))
#define CP_COMMIT() asm volatile("cp.async.commit_group;" ::: "memory")
#define CP_WAIT1() asm volatile("cp.async.wait_group 1;" ::: "memory")
#define ONES_F16X2 0x3C003C00u

// ---------------- fp32 -> fp16 conversion (init fused) ----------------
__global__ __launch_bounds__(256) void convert_x(const float* __restrict__ X) {
    if (blockIdx.x == 0 && threadIdx.x < 5) g_mx[threadIdx.x] = 0u;
    size_t i4 = ((size_t)blockIdx.x * 256 + threadIdx.x) * 4;
    float4 v = *(const float4*)(X + i4);
    *(__half2*)(g_x16 + i4 + 0) = __floats2half2_rn(v.x, v.y);
    *(__half2*)(g_x16 + i4 + 2) = __floats2half2_rn(v.z, v.w);
}

__global__ __launch_bounds__(256) void convert_w(
    const float* __restrict__ Wq, const float* __restrict__ Wk,
    const float* __restrict__ Wv) {
    const int z = blockIdx.z;
    const float* W = (z == 0) ? Wq : (z == 1) ? Wk : Wv;
    size_t base = (size_t)z * DMODEL * DMODEL;
    size_t i4 = ((size_t)blockIdx.x * 256 + threadIdx.x) * 4;
    float4 v = *(const float4*)(W + i4);
    *(__half2*)(g_w16 + base + i4 + 0) = __floats2half2_rn(v.x, v.y);
    *(__half2*)(g_w16 + base + i4 + 2) = __floats2half2_rn(v.z, v.w);
}

// ---- fp16 QKV GEMM: 256 thr, 2 CTA/SM, K-chunk 64, 3-stage, 1 bar --------
#define GKC 64
#define GST 72                           // smem row stride (fp16), 144B
#define GTILE_B (128 * GST * 2)          // 18432 B per tile
#define GSTG_B (2 * GTILE_B)             // A B = 36864 B per stage
#define GEMM_SMEM_BYTES (3 * GSTG_B)     // 110592

__global__ __launch_bounds__(256, 2) void qkv_gemm_mma(
    const float* __restrict__ bq, const float* __restrict__ bk,
    const float* __restrict__ bv)
{
    extern __shared__ __half sm[];
    __shared__ unsigned s_amax;

    const int tid = threadIdx.x;
    const int wid = tid >> 5;
    const int lane = tid & 31;
    const int g = lane >> 2;
    const int t = lane & 3;
    const int wm = wid & 1;
    const int wn = wid >> 1;

    const int z = blockIdx.z;
    const int m0 = blockIdx.y * 128;
    const int n0 = blockIdx.x * 128;

    const float* __restrict__ bias = (z == 0) ? bq : (z == 1) ? bk : bv;
    __half* __restrict__ O = (z == 0) ? g_q16 : (z == 1) ? g_k16 : g_v16;
    const int mslot = (z == 0) ? 0 : (z == 1) ? 1 : 4;
    const float osc = (z == 0) ? QSCALE : 1.0f;

    const __half* __restrict__ A = g_x16 + (size_t)m0 * DMODEL;
    const __half* __restrict__ B = g_w16 + (size_t)z * DMODEL * DMODEL + (size_t)n0 * DMODEL;

    if (tid == 0) s_amax = 0u;

    const uint32_t sbase = smem_u32(sm);
    const int a_lrow = lane & 15;
    const int a_lcol = ((lane >> 4) & 1) * 8;
    const int b_lrow = (lane & 7) + (lane >> 4) * 8;
    const int b_lcol = ((lane >> 3) & 1) * 8;

    float c[4][4][4];
#pragma unroll
    for (int mt = 0; mt < 4; mt++)
#pragma unroll
        for (int nt = 0; nt < 4; nt++)
#pragma unroll
            for (int r = 0; r < 4; r++) c[mt][nt][r] = 0.f;

    const int NCH = DMODEL / GKC;     // 16

#define GEMM_LOAD_STAGE(ch, st) do {                                          \
        const int k0 = (ch) * GKC;                                            \
        const uint32_t stb = sbase + (uint32_t)(st) * GSTG_B;                 \
        _Pragma("unroll")                                                     \
        for (int i = 0; i < 4; i++) {                                         \
            const int cid = tid + i * 256;                                    \
            const int row = cid >> 3, du = cid & 7;                           \
            const size_t go = (size_t)row * DMODEL + k0 + du * 8;             \
            const uint32_t so = stb + (uint32_t)(row * GST + du * 8) * 2;     \
            CP_ASYNC16(so + 0 * GTILE_B, (const void*)(A + go));              \
            CP_ASYNC16(so + 1 * GTILE_B, (const void*)(B + go));              \
        }                                                                     \
    } while (0)

    GEMM_LOAD_STAGE(0, 0); CP_COMMIT();
    GEMM_LOAD_STAGE(1, 1); CP_COMMIT();

    int st = 0;
    for (int ch = 0; ch < NCH; ch++) {
        CP_WAIT1();
        __syncthreads();   // all warps done with stage (ch-1): safe to refill
        if (ch + 2 < NCH) {
            const int st2 = (st + 2 >= 3) ? st - 1 : st + 2;
            GEMM_LOAD_STAGE(ch + 2, st2);
        }
        CP_COMMIT();

        const uint32_t bA = sbase + (uint32_t)st * GSTG_B;
        const uint32_t bB = bA + GTILE_B;
#pragma unroll
        for (int ks = 0; ks < 4; ks++) {
            const int kc = ks * 16;
            uint32_t ah[4][4];
#pragma unroll
            for (int mt = 0; mt < 4; mt++) {
                const uint32_t off =
                    (uint32_t)(((wm * 64 + mt * 16 + a_lrow) * GST + kc + a_lcol) * 2);
                LDSM_X4(ah[mt][0], ah[mt][1], ah[mt][2], ah[mt][3], bA + off);
            }
            uint32_t bf[4][2];
#pragma unroll
            for (int ntp = 0; ntp < 2; ntp++) {
                const uint32_t off =
                    (uint32_t)(((wn * 32 + ntp * 16 + b_lrow) * GST + kc + b_lcol) * 2);
                LDSM_X4(bf[2 * ntp][0], bf[2 * ntp][1],
                        bf[2 * ntp + 1][0], bf[2 * ntp + 1][1], bB + off);
            }
#pragma unroll
            for (int mt = 0; mt < 4; mt++)
#pragma unroll
                for (int nt = 0; nt < 4; nt++)
                    mma_f16(c[mt][nt], ah[mt], bf[nt][0], bf[nt][1]);
        }
        st = (st + 1 >= 3) ? 0 : st + 1;
    }
#undef GEMM_LOAD_STAGE

    // epilogue: bias, absmax (pre-scale), fp16 store (Q prescaled)
    float lmax = 0.f;
#pragma unroll
    for (int nt = 0; nt < 4; nt++) {
        const int n = n0 + wn * 32 + nt * 8 + 2 * t;
        const float bn0 = bias[n], bn1 = bias[n + 1];
        const int h = n >> 6, d = n & 63;
#pragma unroll
        for (int mt = 0; mt < 4; mt++) {
            const int mr0 = m0 + wm * 64 + mt * 16 + g;
            const int mr1 = mr0 + 8;
            float v0 = c[mt][nt][0] + bn0;
            float v1 = c[mt][nt][1] + bn1;
            float v2 = c[mt][nt][2] + bn0;
            float v3 = c[mt][nt][3] + bn1;
            lmax = fmaxf(lmax, fmaxf(fmaxf(fabsf(v0), fabsf(v1)),
                                     fmaxf(fabsf(v2), fabsf(v3))));
            const int bb0 = mr0 >> 11, s0 = mr0 & 2047;
            const int bb1 = mr1 >> 11, s1 = mr1 & 2047;
            const size_t o0 = (((size_t)(bb0 * HEADS + h)) * SEQ + s0) * HDIM + d;
            const size_t o1 = (((size_t)(bb1 * HEADS + h)) * SEQ + s1) * HDIM + d;
            *(uint32_t*)(O + o0) = packh(v0 * osc, v1 * osc);
            *(uint32_t*)(O + o1) = packh(v2 * osc, v3 * osc);
        }
    }
    atomicMax(&s_amax, __float_as_uint(lmax));
    __syncthreads();
    if (tid == 0) atomicMax(&g_mx[mslot], s_amax);
}

// ------ flash attention: KV tile 64 (2x32 halves), exp2 half2 P ------------
#define AKV 64                            // kv rows per load tile
#define KST 72                            // smem row stride (fp16), 144B
#define ATILE_B (AKV * KST * 2)           // 9216 B per tile
#define ASTG_B (2 * ATILE_B)              // k v = 18432 B per stage
#define ATTN_SMEM_BYTES (3 * ASTG_B)      // 55296
#define HALF_B (32 * KST * 2)             // 32-row half offset

__global__ __launch_bounds__(256, 2) void attn_mma(float* __restrict__ out)
{
    extern __shared__ __half asm_buf[];
    __shared__ unsigned s_raw, s_aw;

    const int tid = threadIdx.x;
    const int wid = tid >> 5;
    const int lane = tid & 31;
    const int g = lane >> 2;
    const int t = lane & 3;

    const int bh = blockIdx.y;
    const int b = bh >> 4, h = bh & 15;
    const int q0 = blockIdx.x * 128;

    if (tid == 0) { s_raw = 0u; s_aw = 0u; }

    const uint32_t sbase = smem_u32(asm_buf);
    const int b_lrow = (lane & 7) + (lane >> 4) * 8;
    const int b_lcol = ((lane >> 3) & 1) * 8;
    const int v_lrow = (lane & 7) + ((lane >> 3) & 1) * 8;
    const int v_lcol = (lane >> 4) * 8;

    // Q fragments (fp16, prescaled to exp2 domain), loaded once
    const size_t qbase = ((size_t)bh * SEQ + q0 + wid * 16) * HDIM;
    const __half* Qh = g_q16 + qbase;
    uint32_t qh[4][4];
#pragma unroll
    for (int kk = 0; kk < 4; kk++) {
        const int c0 = kk * 16 + 2 * t;
        qh[kk][0] = *(const uint32_t*)(Qh + g * HDIM + c0);
        qh[kk][1] = *(const uint32_t*)(Qh + (g + 8) * HDIM + c0);
        qh[kk][2] = *(const uint32_t*)(Qh + g * HDIM + c0 + 8);
        qh[kk][3] = *(const uint32_t*)(Qh + (g + 8) * HDIM + c0 + 8);
    }

    const __half* K = g_k16 + (size_t)bh * SEQ * HDIM;
    const __half* V = g_v16 + (size_t)bh * SEQ * HDIM;

    float o[8][4];
#pragma unroll
    for (int j = 0; j < 8; j++)
#pragma unroll
        for (int r = 0; r < 4; r++) o[j][r] = 0.f;
    float lac[4] = {0.f, 0.f, 0.f, 0.f};
    float m0 = -1e30f, m1 = -1e30f, raw = 0.f;

    const int NKV = SEQ / AKV;  // 32

    // 64 rows x 128B per matrix / 256 thr: 2 x 16B per matrix per thread
#define ATTN_LOAD_STAGE(kv, st) do {                                          \
        const int base_row = (kv) * AKV;                                      \
        const uint32_t stb = sbase + (uint32_t)(st) * ASTG_B;                 \
        _Pragma("unroll")                                                     \
        for (int i = 0; i < 2; i++) {                                         \
            const int cid = tid + i * 256;                                    \
            const int row = cid >> 3, du = cid & 7;                           \
            const size_t go = (size_t)(base_row + row) * HDIM + du * 8;       \
            const uint32_t so = stb + (uint32_t)(row * KST + du * 8) * 2;     \
            CP_ASYNC16(so + 0 * ATILE_B, (const void*)(K + go));              \
            CP_ASYNC16(so + 1 * ATILE_B, (const void*)(V + go));              \
        }                                                                     \
    } while (0)

    ATTN_LOAD_STAGE(0, 0); CP_COMMIT();
    ATTN_LOAD_STAGE(1, 1); CP_COMMIT();

    int st = 0;
    for (int kv = 0; kv < NKV; kv++) {
        CP_WAIT1();
        __syncthreads();
        if (kv + 2 < NKV) {
            const int st2 = (st + 2 >= 3) ? st - 1 : st + 2;
            ATTN_LOAD_STAGE(kv + 2, st2);
        }
        CP_COMMIT();

        const uint32_t stg = sbase + (uint32_t)st * ASTG_B;

#pragma unroll
        for (int hf = 0; hf < 2; hf++) {
            const uint32_t k_b = stg + hf * HALF_B;
            const uint32_t v_b = stg + ATILE_B + hf * HALF_B;

            // S2 = Qs·K^T (scores already in exp2 domain)
            float s[4][4];
#pragma unroll
            for (int j = 0; j < 4; j++)
#pragma unroll
                for (int r = 0; r < 4; r++) s[j][r] = 0.f;
#pragma unroll
            for (int kk = 0; kk < 4; kk++) {
                uint32_t kb[4][2];
#pragma unroll
                for (int jp = 0; jp < 2; jp++) {
                    const uint32_t off =
                        (uint32_t)(((jp * 16 + b_lrow) * KST + kk * 16 + b_lcol) * 2);
                    LDSM_X4(kb[2 * jp][0], kb[2 * jp][1],
                            kb[2 * jp + 1][0], kb[2 * jp + 1][1], k_b + off);
                }
#pragma unroll
                for (int j = 0; j < 4; j++)
                    mma_f16(s[j], qh[kk], kb[j][0], kb[j][1]);
            }

            // absmax, online max
            float rm0 = -1e30f, rm1 = -1e30f;
#pragma unroll
            for (int j = 0; j < 4; j++) {
#pragma unroll
                for (int r = 0; r < 4; r++)
                    raw = fmaxf(raw, fabsf(s[j][r]));
                rm0 = fmaxf(rm0, fmaxf(s[j][0], s[j][1]));
                rm1 = fmaxf(rm1, fmaxf(s[j][2], s[j][3]));
            }
            rm0 = fmaxf(rm0, __shfl_xor_sync(0xffffffffu, rm0, 1));
            rm0 = fmaxf(rm0, __shfl_xor_sync(0xffffffffu, rm0, 2));
            rm1 = fmaxf(rm1, __shfl_xor_sync(0xffffffffu, rm1, 1));
            rm1 = fmaxf(rm1, __shfl_xor_sync(0xffffffffu, rm1, 2));
            const float mn0 = fmaxf(m0, rm0), mn1 = fmaxf(m1, rm1);
            const bool upd = (mn0 > m0) || (mn1 > m1);
            if (__any_sync(0xffffffffu, upd)) {
                const float f0 = exp2f(m0 - mn0), f1 = exp2f(m1 - mn1);
#pragma unroll
                for (int j = 0; j < 8; j++) {
                    o[j][0] *= f0; o[j][1] *= f0;
                    o[j][2] *= f1; o[j][3] *= f1;
                }
                lac[0] *= f0; lac[1] *= f0;
                lac[2] *= f1; lac[3] *= f1;
                m0 = mn0; m1 = mn1;
            }

            // P fragments directly in half2 via ex2.approx.f16x2
            uint32_t ph[4][2];
#pragma unroll
            for (int j = 0; j < 4; j++) {
                ph[j][0] = ex2_h2(packh(s[j][0] - m0, s[j][1] - m0));
                ph[j][1] = ex2_h2(packh(s[j][2] - m1, s[j][3] - m1));
            }

            // O += P·V + l += P·1 via extra MMA
#pragma unroll
            for (int kk = 0; kk < 2; kk++) {
                uint32_t pah[4] = {ph[2 * kk][0], ph[2 * kk][1],
                                   ph[2 * kk + 1][0], ph[2 * kk + 1][1]};
                uint32_t vb[8][2];
#pragma unroll
                for (int jp = 0; jp < 4; jp++) {
                    const uint32_t off =
                        (uint32_t)(((kk * 16 + v_lrow) * KST + jp * 16 + v_lcol) * 2);
                    LDSM_X4_T(vb[2 * jp][0], vb[2 * jp][1],
                              vb[2 * jp + 1][0], vb[2 * jp + 1][1], v_b + off);
                }
#pragma unroll
                for (int j = 0; j < 8; j++)
                    mma_f16(o[j], pah, vb[j][0], vb[j][1]);
                mma_f16(lac, pah, ONES_F16X2, ONES_F16X2);
            }
        }
        st = (st + 1 >= 3) ? 0 : st + 1;
    }
#undef ATTN_LOAD_STAGE

    // epilogue
    const float i0 = 1.f / lac[0], i1 = 1.f / lac[2];
    const int r0g = q0 + wid * 16 + g;
    const int r1g = r0g + 8;
    const size_t ob0 = ((size_t)b * SEQ + r0g) * DMODEL + h * HDIM;
    const size_t ob1 = ((size_t)b * SEQ + r1g) * DMODEL + h * HDIM;
#pragma unroll
    for (int j = 0; j < 8; j++) {
        const int d = 8 * j + 2 * t;
        float2 w0 = {o[j][0] * i0, o[j][1] * i0};
        float2 w1 = {o[j][2] * i1, o[j][3] * i1};
        *(float2*)(out + ob0 + d) = w0;
        *(float2*)(out + ob1 + d) = w1;
    }
    atomicMax(&s_raw, __float_as_uint(raw * RAWSCALE));
    atomicMax(&s_aw, __float_as_uint(fmaxf(i0, i1)));
    __syncthreads();
    if (tid == 0) {
        atomicMax(&g_mx[2], s_raw);
        atomicMax(&g_mx[3], s_aw);
    }
}

// ---------------- finalize scalars ----------------
__global__ void finalize_kernel(float* __restrict__ out, int base)
{
    if (threadIdx.x == 0) {
        const float qm  = __uint_as_float(g_mx[0]);
        const float km  = __uint_as_float(g_mx[1]);
        const float qkm = __uint_as_float(g_mx[2]);
        const float awm = __uint_as_float(g_mx[3]);
        const float vm  = __uint_as_float(g_mx[4]);
        out[base + 0] = qm;
        out[base + 1] = km;
        out[base + 2] = qkm;
        out[base + 3] = awm;
        out[base + 4] = vm;
        out[base + 5] = awm;  // v_out_max (faithful source bug)
    }
}

// ---------------- launch ----------------
extern "C" void kernel_launch(void* const* d_in, const int* in_sizes, int n_in,
                              void* d_out, int out_size)
{
    const float* X  = (const float*)d_in[0];
    const float* Wq = (const float*)d_in[1];
    const float* bq = (const float*)d_in[2];
    const float* Wk = (const float*)d_in[3];
    const float* bk = (const float*)d_in[4];
    const float* Wv = (const float*)d_in[5];
    const float* bv = (const float*)d_in[6];
    float* out = (float*)d_out;

    cudaFuncSetAttribute(qkv_gemm_mma,
                         cudaFuncAttributeMaxDynamicSharedMemorySize,
                         GEMM_SMEM_BYTES);
    cudaFuncSetAttribute(attn_mma,
                         cudaFuncAttributeMaxDynamicSharedMemorySize,
                         ATTN_SMEM_BYTES);

    convert_x<<<MROWS * DMODEL / 4 / 256, 256>>>(X);                    // 0
    convert_w<<<dim3(DMODEL * DMODEL / 4 / 256, 1, 3), 256>>>(Wq, Wk, Wv); // 1
    qkv_gemm_mma<<<dim3(DMODEL / 128, MROWS / 128, 3), 256,
                   GEMM_SMEM_BYTES>>>(bq, bk, bv);                      // 2
    attn_mma<<<dim3(SEQ / 128, BATCH * HEADS), 256,
               ATTN_SMEM_BYTES>>>(out);                                 // 3
    finalize_kernel<<<1, 32>>>(out, out_size - 6);                      // 4
}

// round 16
// speedup vs baseline: 1.0222x; 1.0222x over previous
#include <cuda_runtime.h>
#include <cuda_fp16.h>
#include <cstdint>

// Problem constants: B=2, S=2048, DM=1024, H=16, DH=64
#define BATCH 2
#define SEQ 2048
#define DMODEL 1024
#define HEADS 16
#define HDIM 64
#define MROWS (BATCH*SEQ)                 // 4096
#define QKV_ELEMS (BATCH*HEADS*SEQ*HDIM)  // 4,194,304

// Q prescale: 0.125 * log2(e)  (scores arrive in exp2 domain)
#define QSCALE 0.18033688011112042f
#define RAWSCALE 5.5451774444795623f

// ---------------- device scratch (fp16) ----------------
__device__ __half g_x16[MROWS * DMODEL];
__device__ __half g_w16[3 * DMODEL * DMODEL];
__device__ __half g_q16[QKV_ELEMS];
__device__ __half g_k16[QKV_ELEMS];
__device__ __half g_v16[QKV_ELEMS];
// absmax slots: 0=q 1=k 2=qk_raw 3=aw 4=v
__device__ unsigned g_mx[5];

// ---------------- helpers ----------------
__device__ __forceinline__ void mma_f16(float (&c)[4], const uint32_t (&a)[4],
                                        uint32_t b0, uint32_t b1) {
    asm volatile(
        "mma.sync.aligned.m16n8k16.row.col.f32.f16.f16.f32 "
        "{%0,%1,%2,%3}, {%4,%5,%6,%7}, {%8,%9}, {%0,%1,%2,%3};"
        : "+f"(c[0]), "+f"(c[1]), "+f"(c[2]), "+f"(c[3])
        : "r"(a[0]), "r"(a[1]), "r"(a[2]), "r"(a[3]), "r"(b0), "r"(b1));
}
__device__ __forceinline__ uint32_t packh(float lo, float hi) {
    uint32_t r;
    asm("cvt.rn.f16x2.f32 %0, %1, %2;" : "=r"(r) : "f"(hi), "f"(lo));
    return r;
}
__device__ __forceinline__ uint32_t ex2_h2(uint32_t a) {
    uint32_t r;
    asm("ex2.approx.f16x2 %0, %1;" : "=r"(r) : "r"(a));
    return r;
}
__device__ __forceinline__ uint32_t smem_u32(const void* p) {
    uint32_t a;
    asm("{ .reg .u64 t; cvta.to.shared.u64 t, %1; cvt.u32.u64 %0, t; }"
        : "=r"(a) : "l"(p));
    return a;
}
#define LDSM_X4(r0, r1, r2, r3, addr) \
    asm volatile("ldmatrix.sync.aligned.m8n8.x4.shared.b16 {%0,%1,%2,%3}, [%4];" \
                 : "=r"(r0), "=r"(r1), "=r"(r2), "=r"(r3) : "r"(addr))
#define LDSM_X4_T(r0, r1, r2, r3, addr) \
    asm volatile("ldmatrix.sync.aligned.m8n8.x4.trans.shared.b16 {%0,%1,%2,%3}, [%4];" \
                 : "=r"(r0), "=r"(r1), "=r"(r2), "=r"(r3) : "r"(addr))
#define CP_ASYNC16(dst, src) \
    asm volatile("cp.async.cg.shared.global [%0], [%1], 16;" \
                 :: "r"(dst), "l"(src))
#define CP_COMMIT() asm volatile("cp.async.commit_group;" ::: "memory")
#define CP_WAIT1() asm volatile("cp.async.wait_group 1;" ::: "memory")
#define ONES_F16X2 0x3C003C00u

// -------- fused fp32 -> fp16 conversion (X + all W in one launch) ----------
#define XBLKS (MROWS * DMODEL / 1024)          // 4096
#define WBLKS (3 * DMODEL * DMODEL / 1024)     // 3072

__global__ __launch_bounds__(256) void convert_all(
    const float* __restrict__ X,
    const float* __restrict__ Wq, const float* __restrict__ Wk,
    const float* __restrict__ Wv) {
    const int bid = blockIdx.x;
    if (bid == 0 && threadIdx.x < 5) g_mx[threadIdx.x] = 0u;
    if (bid < XBLKS) {
        size_t i4 = ((size_t)bid * 256 + threadIdx.x) * 4;
        float4 v = *(const float4*)(X + i4);
        *(__half2*)(g_x16 + i4 + 0) = __floats2half2_rn(v.x, v.y);
        *(__half2*)(g_x16 + i4 + 2) = __floats2half2_rn(v.z, v.w);
    } else {
        const int wb = bid - XBLKS;
        const int z = wb / (WBLKS / 3);
        const float* W = (z == 0) ? Wq : (z == 1) ? Wk : Wv;
        const size_t zoff = (size_t)(wb % (WBLKS / 3)) * 1024 +
                            (size_t)threadIdx.x * 4;
        float4 v = *(const float4*)(W + zoff);
        __half* dst = g_w16 + (size_t)z * DMODEL * DMODEL + zoff;
        *(__half2*)(dst + 0) = __floats2half2_rn(v.x, v.y);
        *(__half2*)(dst + 2) = __floats2half2_rn(v.z, v.w);
    }
}

// ---- fp16 1-pass QKV GEMM: 256 thr, 2 CTA/SM, K-chunk 64, 2-stage ---------
#define GKC 64
#define GST 72                           // smem row stride (fp16), 144B
#define GTILE_B (128 * GST * 2)          // 18432 B per tile
#define GSTG_B (2 * GTILE_B)             // A B = 36864 B per stage
#define GEMM_SMEM_BYTES (2 * GSTG_B)     // 73728

__global__ __launch_bounds__(256, 2) void qkv_gemm_mma(
    const float* __restrict__ bq, const float* __restrict__ bk,
    const float* __restrict__ bv)
{
    extern __shared__ __half sm[];
    __shared__ unsigned s_amax;

    const int tid = threadIdx.x;
    const int wid = tid >> 5;
    const int lane = tid & 31;
    const int g = lane >> 2;
    const int t = lane & 3;
    const int wm = wid & 1;
    const int wn = wid >> 1;

    const int z = blockIdx.z;
    const int m0 = blockIdx.y * 128;
    const int n0 = blockIdx.x * 128;

    const float* __restrict__ bias = (z == 0) ? bq : (z == 1) ? bk : bv;
    __half* __restrict__ O = (z == 0) ? g_q16 : (z == 1) ? g_k16 : g_v16;
    const int mslot = (z == 0) ? 0 : (z == 1) ? 1 : 4;
    const float osc = (z == 0) ? QSCALE : 1.0f;

    const __half* __restrict__ A = g_x16 + (size_t)m0 * DMODEL;
    const __half* __restrict__ B = g_w16 + (size_t)z * DMODEL * DMODEL + (size_t)n0 * DMODEL;

    if (tid == 0) s_amax = 0u;

    const uint32_t sbase = smem_u32(sm);
    const int a_lrow = lane & 15;
    const int a_lcol = ((lane >> 4) & 1) * 8;
    const int b_lrow = (lane & 7) + (lane >> 4) * 8;
    const int b_lcol = ((lane >> 3) & 1) * 8;

    float c[4][4][4];
#pragma unroll
    for (int mt = 0; mt < 4; mt++)
#pragma unroll
        for (int nt = 0; nt < 4; nt++)
#pragma unroll
            for (int r = 0; r < 4; r++) c[mt][nt][r] = 0.f;

    const int NCH = DMODEL / GKC;     // 16

#define GEMM_LOAD_STAGE(ch, st) do {                                          \
        const int k0 = (ch) * GKC;                                            \
        const uint32_t stb = sbase + (uint32_t)(st) * GSTG_B;                 \
        _Pragma("unroll")                                                     \
        for (int i = 0; i < 4; i++) {                                         \
            const int cid = tid + i * 256;                                    \
            const int row = cid >> 3, du = cid & 7;                           \
            const size_t go = (size_t)row * DMODEL + k0 + du * 8;             \
            const uint32_t so = stb + (uint32_t)(row * GST + du * 8) * 2;     \
            CP_ASYNC16(so + 0 * GTILE_B, (const void*)(A + go));              \
            CP_ASYNC16(so + 1 * GTILE_B, (const void*)(B + go));              \
        }                                                                     \
    } while (0)

    GEMM_LOAD_STAGE(0, 0); CP_COMMIT();
    GEMM_LOAD_STAGE(1, 1); CP_COMMIT();

    for (int ch = 0; ch < NCH; ch++) {
        CP_WAIT1();
        __syncthreads();
        const int st = ch & 1;
        const uint32_t bA = sbase + (uint32_t)st * GSTG_B;
        const uint32_t bB = bA + GTILE_B;
#pragma unroll
        for (int ks = 0; ks < 4; ks++) {
            const int kc = ks * 16;
            uint32_t ah[4][4];
#pragma unroll
            for (int mt = 0; mt < 4; mt++) {
                const uint32_t off =
                    (uint32_t)(((wm * 64 + mt * 16 + a_lrow) * GST + kc + a_lcol) * 2);
                LDSM_X4(ah[mt][0], ah[mt][1], ah[mt][2], ah[mt][3], bA + off);
            }
            uint32_t bf[4][2];
#pragma unroll
            for (int ntp = 0; ntp < 2; ntp++) {
                const uint32_t off =
                    (uint32_t)(((wn * 32 + ntp * 16 + b_lrow) * GST + kc + b_lcol) * 2);
                LDSM_X4(bf[2 * ntp][0], bf[2 * ntp][1],
                        bf[2 * ntp + 1][0], bf[2 * ntp + 1][1], bB + off);
            }
#pragma unroll
            for (int mt = 0; mt < 4; mt++)
#pragma unroll
                for (int nt = 0; nt < 4; nt++)
                    mma_f16(c[mt][nt], ah[mt], bf[nt][0], bf[nt][1]);
        }
        __syncthreads();
        if (ch + 2 < NCH) {
            GEMM_LOAD_STAGE(ch + 2, st);
            CP_COMMIT();
        }
    }
#undef GEMM_LOAD_STAGE

    // epilogue: bias, absmax (pre-scale), fp16 store (Q prescaled)
    float lmax = 0.f;
#pragma unroll
    for (int nt = 0; nt < 4; nt++) {
        const int n = n0 + wn * 32 + nt * 8 + 2 * t;
        const float bn0 = bias[n], bn1 = bias[n + 1];
        const int h = n >> 6, d = n & 63;
#pragma unroll
        for (int mt = 0; mt < 4; mt++) {
            const int mr0 = m0 + wm * 64 + mt * 16 + g;
            const int mr1 = mr0 + 8;
            float v0 = c[mt][nt][0] + bn0;
            float v1 = c[mt][nt][1] + bn1;
            float v2 = c[mt][nt][2] + bn0;
            float v3 = c[mt][nt][3] + bn1;
            lmax = fmaxf(lmax, fmaxf(fmaxf(fabsf(v0), fabsf(v1)),
                                     fmaxf(fabsf(v2), fabsf(v3))));
            const int bb0 = mr0 >> 11, s0 = mr0 & 2047;
            const int bb1 = mr1 >> 11, s1 = mr1 & 2047;
            const size_t o0 = (((size_t)(bb0 * HEADS + h)) * SEQ + s0) * HDIM + d;
            const size_t o1 = (((size_t)(bb1 * HEADS + h)) * SEQ + s1) * HDIM + d;
            *(uint32_t*)(O + o0) = packh(v0 * osc, v1 * osc);
            *(uint32_t*)(O + o1) = packh(v2 * osc, v3 * osc);
        }
    }
    atomicMax(&s_amax, __float_as_uint(lmax));
    __syncthreads();
    if (tid == 0) atomicMax(&g_mx[mslot], s_amax);
}

// ------ flash attention: exp2 half2 P, rescale-skip, 1 bar/tile ------------
#define AKV 32                            // kv rows per tile
#define KST 72                            // smem row stride (fp16), 144B
#define ATILE_B (AKV * KST * 2)           // 4608 B per tile
#define ASTG_B (2 * ATILE_B)              // k v = 9216 B per stage
#define ATTN_SMEM_BYTES (3 * ASTG_B)      // 27648

__global__ __launch_bounds__(256, 2) void attn_mma(float* __restrict__ out)
{
    extern __shared__ __half asm_buf[];
    __shared__ unsigned s_raw, s_aw;

    const int tid = threadIdx.x;
    const int wid = tid >> 5;
    const int lane = tid & 31;
    const int g = lane >> 2;
    const int t = lane & 3;

    const int bh = blockIdx.y;
    const int b = bh >> 4, h = bh & 15;
    const int q0 = blockIdx.x * 128;

    if (tid == 0) { s_raw = 0u; s_aw = 0u; }

    const uint32_t sbase = smem_u32(asm_buf);
    const int b_lrow = (lane & 7) + (lane >> 4) * 8;
    const int b_lcol = ((lane >> 3) & 1) * 8;
    const int v_lrow = (lane & 7) + ((lane >> 3) & 1) * 8;
    const int v_lcol = (lane >> 4) * 8;

    // Q fragments (fp16, prescaled to exp2 domain), loaded once
    const size_t qbase = ((size_t)bh * SEQ + q0 + wid * 16) * HDIM;
    const __half* Qh = g_q16 + qbase;
    uint32_t qh[4][4];
#pragma unroll
    for (int kk = 0; kk < 4; kk++) {
        const int c0 = kk * 16 + 2 * t;
        qh[kk][0] = *(const uint32_t*)(Qh + g * HDIM + c0);
        qh[kk][1] = *(const uint32_t*)(Qh + (g + 8) * HDIM + c0);
        qh[kk][2] = *(const uint32_t*)(Qh + g * HDIM + c0 + 8);
        qh[kk][3] = *(const uint32_t*)(Qh + (g + 8) * HDIM + c0 + 8);
    }

    const __half* K = g_k16 + (size_t)bh * SEQ * HDIM;
    const __half* V = g_v16 + (size_t)bh * SEQ * HDIM;

    float o[8][4];
#pragma unroll
    for (int j = 0; j < 8; j++)
#pragma unroll
        for (int r = 0; r < 4; r++) o[j][r] = 0.f;
    float lac[4] = {0.f, 0.f, 0.f, 0.f};
    float m0 = -1e30f, m1 = -1e30f, raw = 0.f;

    const int NKV = SEQ / AKV;  // 64

#define ATTN_LOAD_STAGE(kv, st) do {                                          \
        const int base_row = (kv) * AKV;                                      \
        const uint32_t stb = sbase + (uint32_t)(st) * ASTG_B;                 \
        const int row = tid >> 3, du = tid & 7;                               \
        const size_t go = (size_t)(base_row + row) * HDIM + du * 8;           \
        const uint32_t so = stb + (uint32_t)(row * KST + du * 8) * 2;         \
        CP_ASYNC16(so + 0 * ATILE_B, (const void*)(K + go));                  \
        CP_ASYNC16(so + 1 * ATILE_B, (const void*)(V + go));                  \
    } while (0)

    ATTN_LOAD_STAGE(0, 0); CP_COMMIT();
    ATTN_LOAD_STAGE(1, 1); CP_COMMIT();

    int st = 0;
    for (int kv = 0; kv < NKV; kv++) {
        CP_WAIT1();
        __syncthreads();   // single barrier per tile: orders prior-iter reads
        if (kv + 2 < NKV) {
            const int st2 = (st + 2 >= 3) ? st - 1 : st + 2;
            ATTN_LOAD_STAGE(kv + 2, st2);
        }
        CP_COMMIT();

        const uint32_t k_b = sbase + (uint32_t)st * ASTG_B;
        const uint32_t v_b = k_b + ATILE_B;

        // S2 = Qs·K^T (scores already in exp2 domain)
        float s[4][4];
#pragma unroll
        for (int j = 0; j < 4; j++)
#pragma unroll
            for (int r = 0; r < 4; r++) s[j][r] = 0.f;
#pragma unroll
        for (int kk = 0; kk < 4; kk++) {
            uint32_t kb[4][2];
#pragma unroll
            for (int jp = 0; jp < 2; jp++) {
                const uint32_t off =
                    (uint32_t)(((jp * 16 + b_lrow) * KST + kk * 16 + b_lcol) * 2);
                LDSM_X4(kb[2 * jp][0], kb[2 * jp][1],
                        kb[2 * jp + 1][0], kb[2 * jp + 1][1], k_b + off);
            }
#pragma unroll
            for (int j = 0; j < 4; j++)
                mma_f16(s[j], qh[kk], kb[j][0], kb[j][1]);
        }

        // absmax, online max
        float rm0 = -1e30f, rm1 = -1e30f;
#pragma unroll
        for (int j = 0; j < 4; j++) {
#pragma unroll
            for (int r = 0; r < 4; r++)
                raw = fmaxf(raw, fabsf(s[j][r]));
            rm0 = fmaxf(rm0, fmaxf(s[j][0], s[j][1]));
            rm1 = fmaxf(rm1, fmaxf(s[j][2], s[j][3]));
        }
        rm0 = fmaxf(rm0, __shfl_xor_sync(0xffffffffu, rm0, 1));
        rm0 = fmaxf(rm0, __shfl_xor_sync(0xffffffffu, rm0, 2));
        rm1 = fmaxf(rm1, __shfl_xor_sync(0xffffffffu, rm1, 1));
        rm1 = fmaxf(rm1, __shfl_xor_sync(0xffffffffu, rm1, 2));
        const float mn0 = fmaxf(m0, rm0), mn1 = fmaxf(m1, rm1);
        const bool upd = (mn0 > m0) || (mn1 > m1);
        if (__any_sync(0xffffffffu, upd)) {
            const float f0 = exp2f(m0 - mn0), f1 = exp2f(m1 - mn1);
#pragma unroll
            for (int j = 0; j < 8; j++) {
                o[j][0] *= f0; o[j][1] *= f0;
                o[j][2] *= f1; o[j][3] *= f1;
            }
            lac[0] *= f0; lac[1] *= f0;
            lac[2] *= f1; lac[3] *= f1;
            m0 = mn0; m1 = mn1;
        }

        // P fragments directly in half2 via ex2.approx.f16x2
        uint32_t ph[4][2];
#pragma unroll
        for (int j = 0; j < 4; j++) {
            ph[j][0] = ex2_h2(packh(s[j][0] - m0, s[j][1] - m0));
            ph[j][1] = ex2_h2(packh(s[j][2] - m1, s[j][3] - m1));
        }

        // O += P·V + l += P·1 via extra MMA
#pragma unroll
        for (int kk = 0; kk < 2; kk++) {
            uint32_t pah[4] = {ph[2 * kk][0], ph[2 * kk][1],
                               ph[2 * kk + 1][0], ph[2 * kk + 1][1]};
            uint32_t vb[8][2];
#pragma unroll
            for (int jp = 0; jp < 4; jp++) {
                const uint32_t off =
                    (uint32_t)(((kk * 16 + v_lrow) * KST + jp * 16 + v_lcol) * 2);
                LDSM_X4_T(vb[2 * jp][0], vb[2 * jp][1],
                          vb[2 * jp + 1][0], vb[2 * jp + 1][1], v_b + off);
            }
#pragma unroll
            for (int j = 0; j < 8; j++)
                mma_f16(o[j], pah, vb[j][0], vb[j][1]);
            mma_f16(lac, pah, ONES_F16X2, ONES_F16X2);
        }
        st = (st + 1 >= 3) ? 0 : st + 1;
    }
#undef ATTN_LOAD_STAGE

    // epilogue
    const float i0 = 1.f / lac[0], i1 = 1.f / lac[2];
    const int r0g = q0 + wid * 16 + g;
    const int r1g = r0g + 8;
    const size_t ob0 = ((size_t)b * SEQ + r0g) * DMODEL + h * HDIM;
    const size_t ob1 = ((size_t)b * SEQ + r1g) * DMODEL + h * HDIM;
#pragma unroll
    for (int j = 0; j < 8; j++) {
        const int d = 8 * j + 2 * t;
        float2 w0 = {o[j][0] * i0, o[j][1] * i0};
        float2 w1 = {o[j][2] * i1, o[j][3] * i1};
        *(float2*)(out + ob0 + d) = w0;
        *(float2*)(out + ob1 + d) = w1;
    }
    atomicMax(&s_raw, __float_as_uint(raw * RAWSCALE));
    atomicMax(&s_aw, __float_as_uint(fmaxf(i0, i1)));
    __syncthreads();
    if (tid == 0) {
        atomicMax(&g_mx[2], s_raw);
        atomicMax(&g_mx[3], s_aw);
    }
}

// ---------------- finalize scalars ----------------
__global__ void finalize_kernel(float* __restrict__ out, int base)
{
    if (threadIdx.x == 0) {
        const float qm  = __uint_as_float(g_mx[0]);
        const float km  = __uint_as_float(g_mx[1]);
        const float qkm = __uint_as_float(g_mx[2]);
        const float awm = __uint_as_float(g_mx[3]);
        const float vm  = __uint_as_float(g_mx[4]);
        out[base + 0] = qm;
        out[base + 1] = km;
        out[base + 2] = qkm;
        out[base + 3] = awm;
        out[base + 4] = vm;
        out[base + 5] = awm;  // v_out_max (faithful source bug)
    }
}

// ---------------- launch ----------------
extern "C" void kernel_launch(void* const* d_in, const int* in_sizes, int n_in,
                              void* d_out, int out_size)
{
    const float* X  = (const float*)d_in[0];
    const float* Wq = (const float*)d_in[1];
    const float* bq = (const float*)d_in[2];
    const float* Wk = (const float*)d_in[3];
    const float* bk = (const float*)d_in[4];
    const float* Wv = (const float*)d_in[5];
    const float* bv = (const float*)d_in[6];
    float* out = (float*)d_out;

    cudaFuncSetAttribute(qkv_gemm_mma,
                         cudaFuncAttributeMaxDynamicSharedMemorySize,
                         GEMM_SMEM_BYTES);
    cudaFuncSetAttribute(attn_mma,
                         cudaFuncAttributeMaxDynamicSharedMemorySize,
                         ATTN_SMEM_BYTES);

    convert_all<<<XBLKS + WBLKS, 256>>>(X, Wq, Wk, Wv);                 // 0
    qkv_gemm_mma<<<dim3(DMODEL / 128, MROWS / 128, 3), 256,
                   GEMM_SMEM_BYTES>>>(bq, bk, bv);                      // 1
    attn_mma<<<dim3(SEQ / 128, BATCH * HEADS), 256,
               ATTN_SMEM_BYTES>>>(out);                                 // 2
    finalize_kernel<<<1, 32>>>(out, out_size - 6);                      // 3
}